// round 16
// baseline (speedup 1.0000x reference)
#include <cuda_runtime.h>
#include <cuda_fp16.h>
#include <cstdint>

typedef unsigned long long u64;
typedef unsigned int u32;

#define NROWS    262144
#define NCODES   1024
#define NDIM     64
#define MROWS    512              // rows per screen CTA (4 tiles x 16 rows x 8 warps)
#define NCHUNK   64               // codes per sub-chunk
#define NCHUNKS  16
#define CHUNK_BYTES 8448          // 8KB hi frags + 256B csqh
#define CHUNK_U64   1056
#define NSTAGES  8                // 2 sub-chunks per stage
#define STAGE_BYTES (2 * CHUNK_BYTES)
#define SMEM_DYN (2 * STAGE_BYTES)   // 33792
#define MARGIN_S 0.02f            // score-gap margin (10-sigma vs fp16 screen error)
#define RREP     37               // refine replicas (8*37 = 296 CTAs)

// ---- device globals (no allocs allowed) ----
__device__ u64   d_bestkey[NROWS];               // flagged rows: (distbits<<32)|code
__device__ int   d_flag[NROWS];
__device__ int   d_nflag;
__device__ u64   d_cb_blob[NCHUNKS * CHUNK_U64]; // fragment-ordered fp16 codebook (hi) + csqh
__device__ float d_csq[NCODES];
__device__ float d_cbT[NDIM * NCODES];           // transposed codebook for refine

// ---------------- helpers ----------------
__device__ __forceinline__ u32 smem_u32(const void* p) {
    u32 a; asm("{ .reg .u64 t; cvta.to.shared.u64 t, %1; cvt.u32.u64 %0, t; }" : "=r"(a) : "l"(p));
    return a;
}
__device__ __forceinline__ u32 pack2h(float a0, float a1) {
    __half h0 = __float2half_rn(a0), h1 = __float2half_rn(a1);
    return (u32)*(unsigned short*)&h0 | ((u32)*(unsigned short*)&h1 << 16);
}
__device__ __forceinline__ void mma_f32(float* c, const u32* a, u32 b0, u32 b1) {
    asm volatile("mma.sync.aligned.m16n8k16.row.col.f32.f16.f16.f32 "
        "{%0,%1,%2,%3}, {%4,%5,%6,%7}, {%8,%9}, {%0,%1,%2,%3};"
        : "+f"(c[0]), "+f"(c[1]), "+f"(c[2]), "+f"(c[3])
        : "r"(a[0]), "r"(a[1]), "r"(a[2]), "r"(a[3]), "r"(b0), "r"(b1));
}
__device__ __forceinline__ void lds64(u32 addr, u32& x, u32& y) {
    asm volatile("ld.shared.v2.u32 {%0,%1}, [%2];" : "=r"(x), "=r"(y) : "r"(addr));
}
__device__ __forceinline__ void ldsf2(u32 addr, float& x, float& y) {
    asm volatile("ld.shared.v2.f32 {%0,%1}, [%2];" : "=f"(x), "=f"(y) : "r"(addr));
}
__device__ __forceinline__ void cp16(u32 dst, const void* src) {
    asm volatile("cp.async.cg.shared.global [%0], [%1], 16;" :: "r"(dst), "l"(src) : "memory");
}
__device__ __forceinline__ void cp_commit() { asm volatile("cp.async.commit_group;" ::: "memory"); }
__device__ __forceinline__ void upd(float s, int code, float& b1, float& b2, int& i1) {
    if (s > b1) { b2 = b1; b1 = s; i1 = code; } else b2 = fmaxf(b2, s);
}

// ---------------- K0: prep via smem transpose (coalesced stores) ----------------
__global__ void __launch_bounds__(256)
vq_prep(const float* __restrict__ cb) {
    __shared__ float s[64][65];   // 65-float pitch: conflict-free column reads
    const int tid = threadIdx.x, cta = blockIdx.x;
    const int code0 = cta * NCHUNK;

    if (cta == 0 && tid == 0) d_nflag = 0;

    for (int i = tid; i < 64 * NDIM; i += 256)
        s[i >> 6][i & 63] = cb[(size_t)code0 * NDIM + i];
    __syncthreads();

    if (tid < 64) {
        float ssum = 0.f;
        #pragma unroll
        for (int t = 0; t < 16; t++) {
            float vx = s[tid][4*t], vy = s[tid][4*t+1], vz = s[tid][4*t+2], vw = s[tid][4*t+3];
            ssum = __fadd_rn(ssum, __fmul_rn(vx, vx));
            ssum = __fadd_rn(ssum, __fmul_rn(vy, vy));
            ssum = __fadd_rn(ssum, __fmul_rn(vz, vz));
            ssum = __fadd_rn(ssum, __fmul_rn(vw, vw));
        }
        d_csq[code0 + tid] = ssum;
        ((float*)d_cb_blob)[cta * (CHUNK_BYTES / 4) + 2048 + tid] = -0.5f * ssum;
    }

    for (int u = tid; u < 1024; u += 256) {
        int lane = u & 31, nt = (u >> 5) & 7, ks = u >> 8;
        int cl = nt * 8 + (lane >> 2);
        int k0 = ks * 16 + (lane & 3) * 2;
        float a0 = s[cl][k0], a1 = s[cl][k0+1];
        float b0 = s[cl][k0+8], b1v = s[cl][k0+9];
        d_cb_blob[(size_t)cta * CHUNK_U64 + u] =
            (u64)pack2h(a0, a1) | ((u64)pack2h(b0, b1v) << 32);
    }

    for (int i = tid; i < 64 * NDIM; i += 256) {
        int d = i >> 6, cl = i & 63;
        d_cbT[d * NCODES + code0 + cl] = s[cl][d];
    }
}

// ---------------- K1: HMMA screen, 4 A-tiles per warp (halved smem traffic) ----------------
__global__ void __launch_bounds__(256, 1)
vq_screen(const float* __restrict__ inputs, const float* __restrict__ cb,
          float* __restrict__ out) {
    extern __shared__ char smem[];
    const u32 sbase = smem_u32(smem);
    const int tid = threadIdx.x, wid = tid >> 5, lane = tid & 31;
    const int q = lane & 3, rg = lane >> 2;
    const int ctaRow0 = blockIdx.x * MROWS;

    // prefetch stage 0 (chunks 0,1)
    {
        const char* src = (const char*)d_cb_blob;
        for (int j = tid; j < STAGE_BYTES / 16; j += 256)
            cp16(sbase + (u32)j * 16u, src + (size_t)j * 16);
        cp_commit();
    }

    // build A fragments in registers (fp16), 4 tiles of 16 rows per warp
    u32 Ahi[4][4][4];
    #pragma unroll
    for (int t = 0; t < 4; t++) {
        const float* pA = inputs + (size_t)(ctaRow0 + wid * 64 + t * 16 + rg) * NDIM;
        const float* pB = pA + 8 * NDIM;
        #pragma unroll
        for (int ks = 0; ks < 4; ks++) {
            int k0 = ks * 16 + q * 2;
            float2 a0 = *(const float2*)(pA + k0);
            float2 a1 = *(const float2*)(pB + k0);
            float2 a2 = *(const float2*)(pA + k0 + 8);
            float2 a3 = *(const float2*)(pB + k0 + 8);
            Ahi[t][ks][0] = pack2h(a0.x, a0.y);
            Ahi[t][ks][1] = pack2h(a1.x, a1.y);
            Ahi[t][ks][2] = pack2h(a2.x, a2.y);
            Ahi[t][ks][3] = pack2h(a3.x, a3.y);
        }
    }

    float b1[8], b2[8];
    int   i1[8];
    #pragma unroll
    for (int s = 0; s < 8; s++) { b1[s] = -3.4e38f; b2[s] = -3.4e38f; i1[s] = 0; }

    for (int st = 0; st < NSTAGES; st++) {
        if (st + 1 < NSTAGES) {
            u32 dst = sbase + (u32)((st + 1) & 1) * STAGE_BYTES;
            const char* src = (const char*)d_cb_blob + (size_t)(st + 1) * STAGE_BYTES;
            for (int j = tid; j < STAGE_BYTES / 16; j += 256)
                cp16(dst + (u32)j * 16u, src + (size_t)j * 16);
            cp_commit();
            asm volatile("cp.async.wait_group 1;" ::: "memory");
        } else {
            asm volatile("cp.async.wait_group 0;" ::: "memory");
        }
        __syncthreads();

        #pragma unroll
        for (int sub = 0; sub < 2; sub++) {
            const u32 bbase = sbase + (u32)(st & 1) * STAGE_BYTES + (u32)sub * CHUNK_BYTES;
            const int cbase = (st * 2 + sub) * NCHUNK;

            #pragma unroll
            for (int np = 0; np < 4; np++) {
                const int nt0 = 2 * np, nt1 = nt0 + 1;
                float q00, q01, q10, q11;
                ldsf2(bbase + 8192u + (u32)((nt0 * 8 + q * 2) * 4), q00, q01);
                ldsf2(bbase + 8192u + (u32)((nt1 * 8 + q * 2) * 4), q10, q11);
                // C[t][nt][4], csqh folded into accumulator init
                float C0[4][4], C1[4][4];
                #pragma unroll
                for (int t = 0; t < 4; t++) {
                    C0[t][0] = q00; C0[t][1] = q01; C0[t][2] = q00; C0[t][3] = q01;
                    C1[t][0] = q10; C1[t][1] = q11; C1[t][2] = q10; C1[t][3] = q11;
                }
                u32 x0, x1, y0, y1;
                #pragma unroll
                for (int ks = 0; ks < 4; ks++) {
                    lds64(bbase + (u32)(((ks * 8 + nt0) * 32 + lane) * 8), x0, x1);
                    lds64(bbase + (u32)(((ks * 8 + nt1) * 32 + lane) * 8), y0, y1);
                    #pragma unroll
                    for (int t = 0; t < 4; t++) {
                        mma_f32(C0[t], Ahi[t][ks], x0, x1);
                        mma_f32(C1[t], Ahi[t][ks], y0, y1);
                    }
                }
                const int n00 = cbase + nt0 * 8 + q * 2;
                const int n10 = cbase + nt1 * 8 + q * 2;
                #pragma unroll
                for (int t = 0; t < 4; t++) {
                    upd(C0[t][0], n00,     b1[t*2],   b2[t*2],   i1[t*2]);
                    upd(C0[t][1], n00 + 1, b1[t*2],   b2[t*2],   i1[t*2]);
                    upd(C0[t][2], n00,     b1[t*2+1], b2[t*2+1], i1[t*2+1]);
                    upd(C0[t][3], n00 + 1, b1[t*2+1], b2[t*2+1], i1[t*2+1]);
                    upd(C1[t][0], n10,     b1[t*2],   b2[t*2],   i1[t*2]);
                    upd(C1[t][1], n10 + 1, b1[t*2],   b2[t*2],   i1[t*2]);
                    upd(C1[t][2], n10,     b1[t*2+1], b2[t*2+1], i1[t*2+1]);
                    upd(C1[t][3], n10 + 1, b1[t*2+1], b2[t*2+1], i1[t*2+1]);
                }
            }
        }
        __syncthreads();
    }

    // merge top-2 across the 4 lanes sharing each row
    #pragma unroll
    for (int o = 1; o <= 2; o <<= 1) {
        #pragma unroll
        for (int s = 0; s < 8; s++) {
            float o1 = __shfl_xor_sync(0xffffffffu, b1[s], o);
            float o2 = __shfl_xor_sync(0xffffffffu, b2[s], o);
            int   oi = __shfl_xor_sync(0xffffffffu, i1[s], o);
            float mn = fminf(b1[s], o1);
            b2[s] = fmaxf(fmaxf(b2[s], o2), mn);
            if (o1 > b1[s]) { b1[s] = o1; i1[s] = oi; }
        }
    }

    // finalize: unflagged -> direct output; flagged -> queue for refine
    #pragma unroll
    for (int s = 0; s < 8; s++) {
        int t = s >> 1, h = s & 1;
        int row = ctaRow0 + wid * 64 + t * 16 + h * 8 + rg;
        if (b1[s] - b2[s] < MARGIN_S) {
            if (q == 0) {
                d_bestkey[row] = ~0ULL;
                int p = atomicAdd(&d_nflag, 1);
                d_flag[p] = row;
            }
        } else {
            const float4* src = (const float4*)cb + (size_t)i1[s] * 16 + q * 4;
            float4* dst = (float4*)out + (size_t)row * 16 + q * 4;
            dst[0] = src[0]; dst[1] = src[1]; dst[2] = src[2]; dst[3] = src[3];
        }
    }
}

// ---------------- K2: exact refine (bitwise r11/r14) ----------------
__global__ void __launch_bounds__(256, 2)
vq_refine(const float* __restrict__ inputs) {
    __shared__ float s_cb[NDIM * 128];   // [d][128] slice, 32KB
    __shared__ float s_csq[128];
    const int n = d_nflag;
    if (n == 0) return;
    const int tid  = threadIdx.x, wid = tid >> 5, lane = tid & 31;
    const int slice = blockIdx.x & 7, rep = blockIdx.x >> 3;   // 8 slices x RREP
    const int code0 = slice * 128;

    for (int idx = tid; idx < NDIM * 128; idx += 256)
        s_cb[idx] = d_cbT[(idx >> 7) * NCODES + code0 + (idx & 127)];
    if (tid < 128) s_csq[tid] = d_csq[code0 + tid];
    __syncthreads();

    const int nquads = (n + 3) >> 2;
    const int gw = rep * 8 + wid;
    for (int qd = gw; qd < nquads; qd += RREP * 8) {
        int rows[4]; const float4* xp[4];
        #pragma unroll
        for (int j = 0; j < 4; j++) {
            int fi = 4 * qd + j; if (fi >= n) fi = n - 1;
            rows[j] = d_flag[fi];
            xp[j]   = (const float4*)(inputs + (size_t)rows[j] * NDIM);
        }
        float acc[4][4], xs[4];
        #pragma unroll
        for (int j = 0; j < 4; j++) {
            xs[j] = 0.f;
            #pragma unroll
            for (int k = 0; k < 4; k++) acc[j][k] = 0.f;
        }

        #pragma unroll 4
        for (int d4 = 0; d4 < NDIM / 4; d4++) {
            float4 xq[4];
            #pragma unroll
            for (int j = 0; j < 4; j++) xq[j] = __ldg(xp[j] + d4);
            #pragma unroll
            for (int e = 0; e < 4; e++) {
                const int d = 4 * d4 + e;
                float4 c4 = *(const float4*)&s_cb[d * 128 + lane * 4];
                #pragma unroll
                for (int j = 0; j < 4; j++) {
                    float xv = (e == 0) ? xq[j].x : (e == 1) ? xq[j].y : (e == 2) ? xq[j].z : xq[j].w;
                    xs[j]     = __fmaf_rn(xv, xv,   xs[j]);      // ascending-d, bitwise r7
                    acc[j][0] = __fmaf_rn(xv, c4.x, acc[j][0]);
                    acc[j][1] = __fmaf_rn(xv, c4.y, acc[j][1]);
                    acc[j][2] = __fmaf_rn(xv, c4.z, acc[j][2]);
                    acc[j][3] = __fmaf_rn(xv, c4.w, acc[j][3]);
                }
            }
        }
        #pragma unroll
        for (int j = 0; j < 4; j++) {
            u64 key = ~0ULL;
            #pragma unroll
            for (int k = 0; k < 4; k++) {
                int c = code0 + lane * 4 + k;
                float dist = __fadd_rn(__fsub_rn(xs[j], __fmul_rn(2.0f, acc[j][k])), s_csq[lane * 4 + k]);
                dist = fmaxf(dist, 0.0f);
                u64 kk = ((u64)__float_as_uint(dist) << 32) | (u32)c;
                key = (kk < key) ? kk : key;
            }
            #pragma unroll
            for (int o = 16; o; o >>= 1) {
                u64 ok = __shfl_xor_sync(0xffffffffu, key, o);
                key = (ok < key) ? ok : key;
            }
            if (lane == 0) atomicMin(&d_bestkey[rows[j]], key);
        }
    }
}

// ---------------- K3: gather flagged rows only ----------------
__global__ void vq_fgather(const float* __restrict__ cb, float* __restrict__ out) {
    const int total = d_nflag * 4;
    const int stride = gridDim.x * blockDim.x;
    for (int t = blockIdx.x * blockDim.x + threadIdx.x; t < total; t += stride) {
        int fi = t >> 2, part = t & 3;
        int row = d_flag[fi];
        u32 bi = (u32)(d_bestkey[row] & 0xFFFFFFFFu);
        const float4* s = (const float4*)cb + (size_t)bi * 16 + part * 4;
        float4* o = (float4*)out + (size_t)row * 16 + part * 4;
        o[0] = s[0]; o[1] = s[1]; o[2] = s[2]; o[3] = s[3];
    }
}

// ---------------- host launch ----------------
extern "C" void kernel_launch(void* const* d_in, const int* in_sizes, int n_in,
                              void* d_out, int out_size)
{
    const float* inputs   = (const float*)d_in[0];
    const float* codebook = (const float*)d_in[1];
    float* out = (float*)d_out;

    cudaFuncSetAttribute(vq_screen, cudaFuncAttributeMaxDynamicSharedMemorySize, SMEM_DYN);

    vq_prep   <<<16, 256>>>(codebook);
    vq_screen <<<NROWS / MROWS, 256, SMEM_DYN>>>(inputs, codebook, out);
    vq_refine <<<8 * RREP, 256>>>(inputs);
    vq_fgather<<<256, 256>>>(codebook, out);
}

// round 17
// speedup vs baseline: 1.1734x; 1.1734x over previous
#include <cuda_runtime.h>
#include <cuda_fp16.h>
#include <cstdint>

typedef unsigned long long u64;
typedef unsigned int u32;

#define NROWS    262144
#define NCODES   1024
#define NDIM     64
#define MROWS    256              // rows per screen CTA
#define NCHUNK   64               // codes per sub-chunk
#define NCHUNKS  16
#define CHUNK_BYTES 8448          // 8KB hi frags + 256B csqh
#define CHUNK_U64   1056
#define NSTAGES  8                // 2 sub-chunks per stage
#define STAGE_BYTES (2 * CHUNK_BYTES)
#define SMEM_DYN (2 * STAGE_BYTES)   // 33792
#define MARGIN_S 0.02f            // score-gap margin (10-sigma vs fp16 screen error)
#define RREP     37               // refine replicas (8*37 = 296 CTAs)

// ---- device globals (no allocs allowed) ----
__device__ u64   d_bestkey[NROWS];               // flagged rows: (distbits<<32)|code
__device__ int   d_flag[NROWS];
__device__ int   d_nflag;
__device__ u64   d_cb_blob[NCHUNKS * CHUNK_U64]; // fragment-ordered fp16 codebook (hi) + csqh
__device__ float d_csq[NCODES];
__device__ float d_cbT[NDIM * NCODES];           // transposed codebook for refine

// ---------------- helpers ----------------
__device__ __forceinline__ u32 smem_u32(const void* p) {
    u32 a; asm("{ .reg .u64 t; cvta.to.shared.u64 t, %1; cvt.u32.u64 %0, t; }" : "=r"(a) : "l"(p));
    return a;
}
__device__ __forceinline__ u32 pack2h(float a0, float a1) {
    __half h0 = __float2half_rn(a0), h1 = __float2half_rn(a1);
    return (u32)*(unsigned short*)&h0 | ((u32)*(unsigned short*)&h1 << 16);
}
__device__ __forceinline__ void mma_f32(float* c, const u32* a, u32 b0, u32 b1) {
    asm volatile("mma.sync.aligned.m16n8k16.row.col.f32.f16.f16.f32 "
        "{%0,%1,%2,%3}, {%4,%5,%6,%7}, {%8,%9}, {%0,%1,%2,%3};"
        : "+f"(c[0]), "+f"(c[1]), "+f"(c[2]), "+f"(c[3])
        : "r"(a[0]), "r"(a[1]), "r"(a[2]), "r"(a[3]), "r"(b0), "r"(b1));
}
__device__ __forceinline__ void lds64(u32 addr, u32& x, u32& y) {
    asm volatile("ld.shared.v2.u32 {%0,%1}, [%2];" : "=r"(x), "=r"(y) : "r"(addr));
}
__device__ __forceinline__ void ldsf2(u32 addr, float& x, float& y) {
    asm volatile("ld.shared.v2.f32 {%0,%1}, [%2];" : "=f"(x), "=f"(y) : "r"(addr));
}
__device__ __forceinline__ void cp16(u32 dst, const void* src) {
    asm volatile("cp.async.cg.shared.global [%0], [%1], 16;" :: "r"(dst), "l"(src) : "memory");
}
__device__ __forceinline__ void cp_commit() { asm volatile("cp.async.commit_group;" ::: "memory"); }
__device__ __forceinline__ void upd(float s, int code, float& b1, float& b2, int& i1) {
    if (s > b1) { b2 = b1; b1 = s; i1 = code; } else b2 = fmaxf(b2, s);
}

// ---------------- K0: prep via smem transpose (coalesced stores) ----------------
__global__ void __launch_bounds__(256)
vq_prep(const float* __restrict__ cb) {
    __shared__ float s[64][65];   // 65-float pitch: conflict-free column reads
    const int tid = threadIdx.x, cta = blockIdx.x;
    const int code0 = cta * NCHUNK;

    if (cta == 0 && tid == 0) d_nflag = 0;

    for (int i = tid; i < 64 * NDIM; i += 256)
        s[i >> 6][i & 63] = cb[(size_t)code0 * NDIM + i];
    __syncthreads();

    if (tid < 64) {
        float ssum = 0.f;
        #pragma unroll
        for (int t = 0; t < 16; t++) {
            float vx = s[tid][4*t], vy = s[tid][4*t+1], vz = s[tid][4*t+2], vw = s[tid][4*t+3];
            ssum = __fadd_rn(ssum, __fmul_rn(vx, vx));
            ssum = __fadd_rn(ssum, __fmul_rn(vy, vy));
            ssum = __fadd_rn(ssum, __fmul_rn(vz, vz));
            ssum = __fadd_rn(ssum, __fmul_rn(vw, vw));
        }
        d_csq[code0 + tid] = ssum;
        ((float*)d_cb_blob)[cta * (CHUNK_BYTES / 4) + 2048 + tid] = -0.5f * ssum;
    }

    for (int u = tid; u < 1024; u += 256) {
        int lane = u & 31, nt = (u >> 5) & 7, ks = u >> 8;
        int cl = nt * 8 + (lane >> 2);
        int k0 = ks * 16 + (lane & 3) * 2;
        float a0 = s[cl][k0], a1 = s[cl][k0+1];
        float b0 = s[cl][k0+8], b1v = s[cl][k0+9];
        d_cb_blob[(size_t)cta * CHUNK_U64 + u] =
            (u64)pack2h(a0, a1) | ((u64)pack2h(b0, b1v) << 32);
    }

    for (int i = tid; i < 64 * NDIM; i += 256) {
        int d = i >> 6, cl = i & 63;
        d_cbT[d * NCODES + code0 + cl] = s[cl][d];
    }
}

// ---------------- K1: HMMA screen (bitwise r14 arithmetic), occupancy 3 ----------------
__global__ void __launch_bounds__(256, 3)
vq_screen(const float* __restrict__ inputs, const float* __restrict__ cb,
          float* __restrict__ out) {
    extern __shared__ char smem[];
    const u32 sbase = smem_u32(smem);
    const int tid = threadIdx.x, wid = tid >> 5, lane = tid & 31;
    const int q = lane & 3, rg = lane >> 2;
    const int ctaRow0 = blockIdx.x * MROWS;

    // prefetch stage 0 (chunks 0,1)
    {
        const char* src = (const char*)d_cb_blob;
        for (int j = tid; j < STAGE_BYTES / 16; j += 256)
            cp16(sbase + (u32)j * 16u, src + (size_t)j * 16);
        cp_commit();
    }

    // build A fragments in registers (fp16), 2 tiles of 16 rows
    u32 Ahi[2][4][4];
    #pragma unroll
    for (int t = 0; t < 2; t++) {
        const float* pA = inputs + (size_t)(ctaRow0 + wid * 32 + t * 16 + rg) * NDIM;
        const float* pB = pA + 8 * NDIM;
        #pragma unroll
        for (int ks = 0; ks < 4; ks++) {
            int k0 = ks * 16 + q * 2;
            float2 a0 = *(const float2*)(pA + k0);
            float2 a1 = *(const float2*)(pB + k0);
            float2 a2 = *(const float2*)(pA + k0 + 8);
            float2 a3 = *(const float2*)(pB + k0 + 8);
            Ahi[t][ks][0] = pack2h(a0.x, a0.y);
            Ahi[t][ks][1] = pack2h(a1.x, a1.y);
            Ahi[t][ks][2] = pack2h(a2.x, a2.y);
            Ahi[t][ks][3] = pack2h(a3.x, a3.y);
        }
    }

    float b1[4], b2[4];
    int   i1[4];
    #pragma unroll
    for (int s = 0; s < 4; s++) { b1[s] = -3.4e38f; b2[s] = -3.4e38f; i1[s] = 0; }

    for (int st = 0; st < NSTAGES; st++) {
        if (st + 1 < NSTAGES) {
            u32 dst = sbase + (u32)((st + 1) & 1) * STAGE_BYTES;
            const char* src = (const char*)d_cb_blob + (size_t)(st + 1) * STAGE_BYTES;
            for (int j = tid; j < STAGE_BYTES / 16; j += 256)
                cp16(dst + (u32)j * 16u, src + (size_t)j * 16);
            cp_commit();
            asm volatile("cp.async.wait_group 1;" ::: "memory");
        } else {
            asm volatile("cp.async.wait_group 0;" ::: "memory");
        }
        __syncthreads();

        #pragma unroll
        for (int sub = 0; sub < 2; sub++) {
            const u32 bbase = sbase + (u32)(st & 1) * STAGE_BYTES + (u32)sub * CHUNK_BYTES;
            const int cbase = (st * 2 + sub) * NCHUNK;

            #pragma unroll
            for (int np = 0; np < 4; np++) {
                const int nt0 = 2 * np, nt1 = nt0 + 1;
                float q00, q01, q10, q11;
                ldsf2(bbase + 8192u + (u32)((nt0 * 8 + q * 2) * 4), q00, q01);
                ldsf2(bbase + 8192u + (u32)((nt1 * 8 + q * 2) * 4), q10, q11);
                float C00[4] = {q00, q01, q00, q01};
                float C01[4] = {q10, q11, q10, q11};
                float C10[4] = {q00, q01, q00, q01};
                float C11[4] = {q10, q11, q10, q11};
                u32 x0, x1, y0, y1;
                #pragma unroll
                for (int ks = 0; ks < 4; ks++) {
                    lds64(bbase + (u32)(((ks * 8 + nt0) * 32 + lane) * 8), x0, x1);
                    lds64(bbase + (u32)(((ks * 8 + nt1) * 32 + lane) * 8), y0, y1);
                    mma_f32(C00, Ahi[0][ks], x0, x1);
                    mma_f32(C01, Ahi[0][ks], y0, y1);
                    mma_f32(C10, Ahi[1][ks], x0, x1);
                    mma_f32(C11, Ahi[1][ks], y0, y1);
                }
                const int n00 = cbase + nt0 * 8 + q * 2;
                const int n10 = cbase + nt1 * 8 + q * 2;
                upd(C00[0], n00,     b1[0], b2[0], i1[0]);
                upd(C00[1], n00 + 1, b1[0], b2[0], i1[0]);
                upd(C00[2], n00,     b1[1], b2[1], i1[1]);
                upd(C00[3], n00 + 1, b1[1], b2[1], i1[1]);
                upd(C01[0], n10,     b1[0], b2[0], i1[0]);
                upd(C01[1], n10 + 1, b1[0], b2[0], i1[0]);
                upd(C01[2], n10,     b1[1], b2[1], i1[1]);
                upd(C01[3], n10 + 1, b1[1], b2[1], i1[1]);
                upd(C10[0], n00,     b1[2], b2[2], i1[2]);
                upd(C10[1], n00 + 1, b1[2], b2[2], i1[2]);
                upd(C10[2], n00,     b1[3], b2[3], i1[3]);
                upd(C10[3], n00 + 1, b1[3], b2[3], i1[3]);
                upd(C11[0], n10,     b1[2], b2[2], i1[2]);
                upd(C11[1], n10 + 1, b1[2], b2[2], i1[2]);
                upd(C11[2], n10,     b1[3], b2[3], i1[3]);
                upd(C11[3], n10 + 1, b1[3], b2[3], i1[3]);
            }
        }
        __syncthreads();
    }

    // merge top-2 across the 4 lanes sharing each row
    #pragma unroll
    for (int o = 1; o <= 2; o <<= 1) {
        #pragma unroll
        for (int s = 0; s < 4; s++) {
            float o1 = __shfl_xor_sync(0xffffffffu, b1[s], o);
            float o2 = __shfl_xor_sync(0xffffffffu, b2[s], o);
            int   oi = __shfl_xor_sync(0xffffffffu, i1[s], o);
            float mn = fminf(b1[s], o1);
            b2[s] = fmaxf(fmaxf(b2[s], o2), mn);
            if (o1 > b1[s]) { b1[s] = o1; i1[s] = oi; }
        }
    }

    // finalize: unflagged -> direct output; flagged -> queue for refine
    #pragma unroll
    for (int s = 0; s < 4; s++) {
        int t = s >> 1, h = s & 1;
        int row = ctaRow0 + wid * 32 + t * 16 + h * 8 + rg;
        if (b1[s] - b2[s] < MARGIN_S) {
            if (q == 0) {
                d_bestkey[row] = ~0ULL;
                int p = atomicAdd(&d_nflag, 1);
                d_flag[p] = row;
            }
        } else {
            const float4* src = (const float4*)cb + (size_t)i1[s] * 16 + q * 4;
            float4* dst = (float4*)out + (size_t)row * 16 + q * 4;
            dst[0] = src[0]; dst[1] = src[1]; dst[2] = src[2]; dst[3] = src[3];
        }
    }
}

// ---------------- K2: exact refine (bitwise r11/r14) ----------------
__global__ void __launch_bounds__(256, 2)
vq_refine(const float* __restrict__ inputs) {
    __shared__ float s_cb[NDIM * 128];   // [d][128] slice, 32KB
    __shared__ float s_csq[128];
    const int n = d_nflag;
    if (n == 0) return;
    const int tid  = threadIdx.x, wid = tid >> 5, lane = tid & 31;
    const int slice = blockIdx.x & 7, rep = blockIdx.x >> 3;   // 8 slices x RREP
    const int code0 = slice * 128;

    for (int idx = tid; idx < NDIM * 128; idx += 256)
        s_cb[idx] = d_cbT[(idx >> 7) * NCODES + code0 + (idx & 127)];
    if (tid < 128) s_csq[tid] = d_csq[code0 + tid];
    __syncthreads();

    const int nquads = (n + 3) >> 2;
    const int gw = rep * 8 + wid;
    for (int qd = gw; qd < nquads; qd += RREP * 8) {
        int rows[4]; const float4* xp[4];
        #pragma unroll
        for (int j = 0; j < 4; j++) {
            int fi = 4 * qd + j; if (fi >= n) fi = n - 1;
            rows[j] = d_flag[fi];
            xp[j]   = (const float4*)(inputs + (size_t)rows[j] * NDIM);
        }
        float acc[4][4], xs[4];
        #pragma unroll
        for (int j = 0; j < 4; j++) {
            xs[j] = 0.f;
            #pragma unroll
            for (int k = 0; k < 4; k++) acc[j][k] = 0.f;
        }

        #pragma unroll 4
        for (int d4 = 0; d4 < NDIM / 4; d4++) {
            float4 xq[4];
            #pragma unroll
            for (int j = 0; j < 4; j++) xq[j] = __ldg(xp[j] + d4);
            #pragma unroll
            for (int e = 0; e < 4; e++) {
                const int d = 4 * d4 + e;
                float4 c4 = *(const float4*)&s_cb[d * 128 + lane * 4];
                #pragma unroll
                for (int j = 0; j < 4; j++) {
                    float xv = (e == 0) ? xq[j].x : (e == 1) ? xq[j].y : (e == 2) ? xq[j].z : xq[j].w;
                    xs[j]     = __fmaf_rn(xv, xv,   xs[j]);      // ascending-d, bitwise r7
                    acc[j][0] = __fmaf_rn(xv, c4.x, acc[j][0]);
                    acc[j][1] = __fmaf_rn(xv, c4.y, acc[j][1]);
                    acc[j][2] = __fmaf_rn(xv, c4.z, acc[j][2]);
                    acc[j][3] = __fmaf_rn(xv, c4.w, acc[j][3]);
                }
            }
        }
        #pragma unroll
        for (int j = 0; j < 4; j++) {
            u64 key = ~0ULL;
            #pragma unroll
            for (int k = 0; k < 4; k++) {
                int c = code0 + lane * 4 + k;
                float dist = __fadd_rn(__fsub_rn(xs[j], __fmul_rn(2.0f, acc[j][k])), s_csq[lane * 4 + k]);
                dist = fmaxf(dist, 0.0f);
                u64 kk = ((u64)__float_as_uint(dist) << 32) | (u32)c;
                key = (kk < key) ? kk : key;
            }
            #pragma unroll
            for (int o = 16; o; o >>= 1) {
                u64 ok = __shfl_xor_sync(0xffffffffu, key, o);
                key = (ok < key) ? ok : key;
            }
            if (lane == 0) atomicMin(&d_bestkey[rows[j]], key);
        }
    }
}

// ---------------- K3: gather flagged rows only ----------------
__global__ void vq_fgather(const float* __restrict__ cb, float* __restrict__ out) {
    const int total = d_nflag * 4;
    const int stride = gridDim.x * blockDim.x;
    for (int t = blockIdx.x * blockDim.x + threadIdx.x; t < total; t += stride) {
        int fi = t >> 2, part = t & 3;
        int row = d_flag[fi];
        u32 bi = (u32)(d_bestkey[row] & 0xFFFFFFFFu);
        const float4* s = (const float4*)cb + (size_t)bi * 16 + part * 4;
        float4* o = (float4*)out + (size_t)row * 16 + part * 4;
        o[0] = s[0]; o[1] = s[1]; o[2] = s[2]; o[3] = s[3];
    }
}

// ---------------- host launch ----------------
extern "C" void kernel_launch(void* const* d_in, const int* in_sizes, int n_in,
                              void* d_out, int out_size)
{
    const float* inputs   = (const float*)d_in[0];
    const float* codebook = (const float*)d_in[1];
    float* out = (float*)d_out;

    cudaFuncSetAttribute(vq_screen, cudaFuncAttributeMaxDynamicSharedMemorySize, SMEM_DYN);

    vq_prep   <<<16, 256>>>(codebook);
    vq_screen <<<NROWS / MROWS, 256, SMEM_DYN>>>(inputs, codebook, out);
    vq_refine <<<8 * RREP, 256>>>(inputs);
    vq_fgather<<<256, 256>>>(codebook, out);
}